// round 8
// baseline (speedup 1.0000x reference)
#include <cuda_runtime.h>

#define T_DATA 100000
#define N_E    500
#define N_I    200
#define SUB    20
#define NB     3
#define TSYN   201

typedef unsigned long long ull;

// ---- conv config ----
#define TTC   4096           // outputs per block (256 thr x 16 consecutive, 2 groups of 8)
#define KP    208            // taps padded to multiple of 8
#define NW2   538            // residue-layout row width in ull: (TTC+KP)/8

// Scratch (device globals: allocation-free rule)
__device__ float g_e[(size_t)SUB * T_DATA];
__device__ float g_i[(size_t)SUB * T_DATA];

// ---- packed f32x2 helpers ----
__device__ __forceinline__ ull pk2(float lo, float hi) {
    ull r;
    asm("mov.b64 %0, {%1, %2};" : "=l"(r) : "f"(lo), "f"(hi));
    return r;
}
__device__ __forceinline__ void upk2(ull v, float& lo, float& hi) {
    asm("mov.b64 {%0, %1}, %2;" : "=f"(lo), "=f"(hi) : "l"(v));
}
__device__ __forceinline__ void fma2(ull& d, ull a, ull b) {
    asm("fma.rn.f32x2 %0, %1, %2, %0;" : "+l"(d) : "l"(a), "l"(b));
}

// ---------------------------------------------------------------------------
// Tall-skinny GEMM body: in[t,s] = sum_j S[t,j] * C[s,j].
// ALL of C resident in smem as subunit pairs (10 x NIN ull) -> zero syncs in
// the main loop. S streamed GMEM->regs one quad (float4) ahead; sequential
// 16B strides make most quads L1 hits. Per (s2, quad): 2x LDS.128 broadcast
// of C + 8 FFMA2 (two rows).
// ---------------------------------------------------------------------------
template <int NIN>
__device__ __forceinline__ void gemm_body(const float* __restrict__ Sg,
                                          const float* __restrict__ Cg,
                                          float* __restrict__ outg,
                                          ull* __restrict__ C_sh) {
    const int tid = threadIdx.x;
    const int t0 = blockIdx.x * 256;

    // stage all of C as pairs: C_sh[s2*NIN + c] = (C[2s2,c], C[2s2+1,c])
    for (int i = tid; i < 10 * NIN; i += 128) {
        int s2 = i / NIN, c = i - s2 * NIN;
        C_sh[i] = pk2(Cg[(2 * s2) * NIN + c], Cg[(2 * s2 + 1) * NIN + c]);
    }
    __syncthreads();

    const int r0 = t0 + tid;
    const int r1 = t0 + tid + 128;
    const bool ok0 = r0 < T_DATA;
    const bool ok1 = r1 < T_DATA;
    const float* __restrict__ q0 = Sg + (size_t)(ok0 ? r0 : 0) * NIN;
    const float* __restrict__ q1 = Sg + (size_t)(ok1 ? r1 : 0) * NIN;

    ull acc0[10], acc1[10];
#pragma unroll
    for (int s2 = 0; s2 < 10; s2++) { acc0[s2] = 0ULL; acc1[s2] = 0ULL; }

    float4 cur0 = *reinterpret_cast<const float4*>(q0);
    float4 cur1 = *reinterpret_cast<const float4*>(q1);

#pragma unroll 2
    for (int c0 = 0; c0 < NIN; c0 += 4) {
        float4 nxt0 = cur0, nxt1 = cur1;
        if (c0 + 4 < NIN) {
            nxt0 = *reinterpret_cast<const float4*>(q0 + c0 + 4);
            nxt1 = *reinterpret_cast<const float4*>(q1 + c0 + 4);
        }
        ull a00 = pk2(cur0.x, cur0.x), a01 = pk2(cur0.y, cur0.y);
        ull a02 = pk2(cur0.z, cur0.z), a03 = pk2(cur0.w, cur0.w);
        ull a10 = pk2(cur1.x, cur1.x), a11 = pk2(cur1.y, cur1.y);
        ull a12 = pk2(cur1.z, cur1.z), a13 = pk2(cur1.w, cur1.w);
#pragma unroll
        for (int s2 = 0; s2 < 10; s2++) {
            ulonglong2 cA = *reinterpret_cast<const ulonglong2*>(&C_sh[s2 * NIN + c0]);
            ulonglong2 cB = *reinterpret_cast<const ulonglong2*>(&C_sh[s2 * NIN + c0 + 2]);
            fma2(acc0[s2], a00, cA.x);
            fma2(acc0[s2], a01, cA.y);
            fma2(acc0[s2], a02, cB.x);
            fma2(acc0[s2], a03, cB.y);
            fma2(acc1[s2], a10, cA.x);
            fma2(acc1[s2], a11, cA.y);
            fma2(acc1[s2], a12, cB.x);
            fma2(acc1[s2], a13, cB.y);
        }
        cur0 = nxt0; cur1 = nxt1;
    }

    // epilogue: planar [s][t], coalesced over tid
    if (ok0) {
#pragma unroll
        for (int s2 = 0; s2 < 10; s2++) {
            float a, b;
            upk2(acc0[s2], a, b);
            outg[(size_t)(2 * s2) * T_DATA + r0]     = a;
            outg[(size_t)(2 * s2 + 1) * T_DATA + r0] = b;
        }
    }
    if (ok1) {
#pragma unroll
        for (int s2 = 0; s2 < 10; s2++) {
            float a, b;
            upk2(acc1[s2], a, b);
            outg[(size_t)(2 * s2) * T_DATA + r1]     = a;
            outg[(size_t)(2 * s2 + 1) * T_DATA + r1] = b;
        }
    }
}

__global__ __launch_bounds__(128, 4) void gemm_kernel(const float* __restrict__ Se,
                                                      const float* __restrict__ Si,
                                                      const float* __restrict__ Ce,
                                                      const float* __restrict__ Ci,
                                                      float* __restrict__ oe,
                                                      float* __restrict__ oi) {
    __shared__ __align__(16) ull C_sh[10 * N_E];   // 40 KB (i path uses 16 KB of it)
    if (blockIdx.y == 0) gemm_body<N_E>(Se, Ce, oe, C_sh);
    else                 gemm_body<N_I>(Si, Ci, oi, C_sh);
}

// ---------------------------------------------------------------------------
// Causal conv, e/i fused through f32x2 lanes, register sliding window.
// Taps computed in-block (alpha-function bank). Thread computes 16
// CONSECUTIVE-ish outputs: two groups of 8 (g=0: t0+8*tid+j, g=1: +2048).
// Per 8-tap block: 4x LDS.128 preload taps, then per tap 16 FFMA2 + 2 slide
// LDS.64 into rotating 8-register windows (static indices, no MOVs).
// Residue-of-8 smem layout keeps all lane patterns conflict-free.
// ---------------------------------------------------------------------------
__global__ __launch_bounds__(256, 2) void conv_kernel(float* __restrict__ out,
                                                      const float* __restrict__ K_syn,
                                                      const float* __restrict__ tau_syn,
                                                      const float* __restrict__ delta_syn) {
    __shared__ __align__(16) ull sh[8 * NW2];   // 4304 packed (e,i) samples, 34.4 KB
    __shared__ __align__(16) ull ksh[KP];       // taps padded to 208 with zeros

    const int s = blockIdx.y;
    const int t0 = blockIdx.x * TTC;
    const int tid = threadIdx.x;
    const size_t sT = (size_t)s * T_DATA;

    // taps: ksh[k] = (kern_e[s,k], kern_i[s,k])
    if (tid < KP) {
        const int k = tid;
        float ae = 0.f, ai = 0.f;
        if (k < TSYN) {
            float tse = fmaxf((float)k - delta_syn[s * 2 + 0], 0.f);
            float tsi = fmaxf((float)k - delta_syn[s * 2 + 1], 0.f);
#pragma unroll
            for (int b = 0; b < NB; b++) {
                float te = tse / expf(tau_syn[b * 2 + 0]);
                float ti = tsi / expf(tau_syn[b * 2 + 1]);
                ae += K_syn[s * 6 + b * 2 + 0] * te * expf(-te);
                ai += K_syn[s * 6 + b * 2 + 1] * ti * expf(-ti);
            }
        }
        ksh[k] = pk2(ae, ai);
    }

    // fill: sample index Lp in [0, 8*NW2); t = t0 - 208 + Lp
    for (int Lp = tid; Lp < 8 * NW2; Lp += 256) {
        int t = t0 - 208 + Lp;
        float e = 0.f, ii = 0.f;
        if (t >= 0 && t < T_DATA) { e = g_e[sT + t]; ii = g_i[sT + t]; }
        sh[(Lp & 7) * NW2 + (Lp >> 3)] = pk2(e, ii);
    }
    __syncthreads();

    // ATG(g,c): sample Lp = 2048*g + 8*tid + c + 8
    //   = sh[(c&7)*NW2 + 256*g + tid + 1 + (c>>3)]   (c>>3 arithmetic, c>=-8)
#define ATG(g, c) sh[((((c) & 7) * NW2)) + 256 * (g) + tid + 1 + ((c) >> 3)]

    ull P[2][8], acc[2][8];
#pragma unroll
    for (int g = 0; g < 2; g++)
#pragma unroll
        for (int j = 0; j < 8; j++) {
            acc[g][j] = 0ULL;
            P[g][j] = ATG(g, 200 + j);   // window for k=0: slot m&7 holds d(m)
        }

#pragma unroll 1
    for (int kb = 0; kb < KP; kb += 8) {
        // preload 8 taps (4x LDS.128)
        ull kv[8];
        {
            ulonglong2 k01 = *reinterpret_cast<const ulonglong2*>(&ksh[kb + 0]);
            ulonglong2 k23 = *reinterpret_cast<const ulonglong2*>(&ksh[kb + 2]);
            ulonglong2 k45 = *reinterpret_cast<const ulonglong2*>(&ksh[kb + 4]);
            ulonglong2 k67 = *reinterpret_cast<const ulonglong2*>(&ksh[kb + 6]);
            kv[0] = k01.x; kv[1] = k01.y; kv[2] = k23.x; kv[3] = k23.y;
            kv[4] = k45.x; kv[5] = k45.y; kv[6] = k67.x; kv[7] = k67.y;
        }
#pragma unroll
        for (int r = 0; r < 8; r++) {
#pragma unroll
            for (int g = 0; g < 2; g++) {
#pragma unroll
                for (int j = 0; j < 8; j++)
                    fma2(acc[g][j], kv[r], P[g][(j - r) & 7]);
                // slide: d(199 - k) into slot (199-k)&7 = 7-r
                P[g][7 - r] = ATG(g, 199 - kb - r);
            }
        }
    }
#undef ATG

#pragma unroll
    for (int g = 0; g < 2; g++)
#pragma unroll
        for (int j = 0; j < 8; j++) {
            int t = t0 + 2048 * g + 8 * tid + j;
            if (t < T_DATA) {
                float lo, hi;
                upk2(acc[g][j], lo, hi);
                out[(size_t)t * SUB + s] = lo + hi;   // e-lane + i-lane
            }
        }
}

// ---------------------------------------------------------------------------
extern "C" void kernel_launch(void* const* d_in, const int* in_sizes, int n_in,
                              void* d_out, int out_size) {
    const float* S_e     = (const float*)d_in[0];
    const float* S_i     = (const float*)d_in[1];
    const float* C_syn_e = (const float*)d_in[2];
    const float* C_syn_i = (const float*)d_in[3];
    const float* K_syn   = (const float*)d_in[4];
    const float* tau_syn = (const float*)d_in[5];
    const float* delta   = (const float*)d_in[6];
    float* out = (float*)d_out;

    (void)in_sizes; (void)n_in; (void)out_size;

    float* ge; cudaGetSymbolAddress((void**)&ge, g_e);
    float* gi; cudaGetSymbolAddress((void**)&gi, g_i);

    dim3 ggrid((T_DATA + 255) / 256, 2);            // 391 x 2 (e and i)
    gemm_kernel<<<ggrid, 128>>>(S_e, S_i, C_syn_e, C_syn_i, ge, gi);

    dim3 cgrid((T_DATA + TTC - 1) / TTC, SUB);      // 25 x 20
    conv_kernel<<<cgrid, 256>>>(out, K_syn, tau_syn, delta);
}

// round 9
// speedup vs baseline: 1.1786x; 1.1786x over previous
#include <cuda_runtime.h>
#include <cstdint>

#define T_DATA 100000
#define N_E    500
#define N_I    200
#define SUB    20
#define NB     3
#define TSYN   201

typedef unsigned long long ull;

// ---- GEMM config ----
#define TGX   256            // threads per block
#define RG    256            // rows per block (1 per thread)
#define KC    20             // k-chunk
#define SBUF  (RG * KC)      // floats per S buffer (5120)
#define C2_BYTES 40960       // (N_E/2)*10 ulonglong2 = 40 KB (i uses 16 KB of it)
#define GEMM_SMEM (C2_BYTES + 2 * SBUF * 4)   // 40 KB C + 40 KB S double buffer

// ---- conv config ----
#define TTC   2048           // outputs per block (256 thr x 8 consecutive)
#define KP    208            // taps padded to multiple of 8
#define NWC   282            // residue-layout row width in ull

// Scratch (device globals: allocation-free rule)
__device__ float g_e[(size_t)SUB * T_DATA];
__device__ float g_i[(size_t)SUB * T_DATA];

// ---- packed f32x2 helpers ----
__device__ __forceinline__ ull pk2(float lo, float hi) {
    ull r;
    asm("mov.b64 %0, {%1, %2};" : "=l"(r) : "f"(lo), "f"(hi));
    return r;
}
__device__ __forceinline__ void upk2(ull v, float& lo, float& hi) {
    asm("mov.b64 {%0, %1}, %2;" : "=f"(lo), "=f"(hi) : "l"(v));
}
__device__ __forceinline__ void fma2(ull& d, ull a, ull b) {
    asm("fma.rn.f32x2 %0, %1, %2, %0;" : "+l"(d) : "l"(a), "l"(b));
}
__device__ __forceinline__ uint32_t smem_u32(const void* p) {
    return (uint32_t)__cvta_generic_to_shared(p);
}
// cp.async 16B with zero-fill when !ok (src_size = 0)
__device__ __forceinline__ void cpa16(uint32_t dst, const float* src, bool ok) {
    int sz = ok ? 16 : 0;
    asm volatile("cp.async.cg.shared.global [%0], [%1], 16, %2;"
                 :: "r"(dst), "l"(src), "r"(sz));
}

// ---------------------------------------------------------------------------
// Tall-skinny GEMM body: in[t,s] = sum_j S[t,j] * C[s,j].
// - All of C resident in smem once, as pairs-of-pairs:
//     C2[cpair*10 + s2] = { pk2(C[2s2,2cp],C[2s2+1,2cp]),
//                           pk2(C[2s2,2cp+1],C[2s2+1,2cp+1]) }
//   -> inner loop reads are uniform (broadcast) LDS.128.
// - S staged by cp.async into a double-buffered smem tile with a COALESCED
//   flat mapping (consecutive lanes -> contiguous 80B runs): full sector use.
// - 1 row/thread: acc = 10 ull = 20 regs; conflict-free LDS.128 row reads
//   (row stride 20 words; 8-lane phase banks 20L mod 32 all distinct).
// ---------------------------------------------------------------------------
template <int NIN>
__device__ __forceinline__ void gemm_body(const float* __restrict__ Sg,
                                          const float* __restrict__ Cg,
                                          float* __restrict__ outg,
                                          char* sm) {
    ulonglong2* __restrict__ C2 = reinterpret_cast<ulonglong2*>(sm);
    float* __restrict__ S_sh = reinterpret_cast<float*>(sm + C2_BYTES);

    const int tid = threadIdx.x;
    const int t0 = blockIdx.x * RG;
    const int row = t0 + tid;
    const bool ok = row < T_DATA;

    // stage all of C (once)
    for (int i = tid; i < (NIN / 2) * 10; i += TGX) {
        int cpair = i / 10, s2 = i - cpair * 10;
        int c0 = 2 * cpair;
        ulonglong2 v;
        v.x = pk2(Cg[(2 * s2) * NIN + c0],     Cg[(2 * s2 + 1) * NIN + c0]);
        v.y = pk2(Cg[(2 * s2) * NIN + c0 + 1], Cg[(2 * s2 + 1) * NIN + c0 + 1]);
        C2[i] = v;
    }

    const uint32_t s_base = smem_u32(S_sh);

    // coalesced chunk stage: 1280 quads, flat = q*256 + tid
#define STAGE(BUF, KCOL)                                                      \
    {                                                                         \
        _Pragma("unroll")                                                     \
        for (int q = 0; q < 5; q++) {                                         \
            int flat = q * TGX + tid;                                         \
            int rl = flat / 5, q5 = flat - rl * 5;                            \
            bool okr = (t0 + rl) < T_DATA;                                    \
            const float* src = Sg + (size_t)(okr ? (t0 + rl) : 0) * NIN       \
                               + (KCOL) + 4 * q5;                             \
            uint32_t dst = s_base +                                           \
                (uint32_t)(((BUF) * SBUF + rl * KC + 4 * q5) * 4);            \
            cpa16(dst, src, okr);                                             \
        }                                                                     \
    }

    ull acc[10];
#pragma unroll
    for (int s2 = 0; s2 < 10; s2++) acc[s2] = 0ULL;

    STAGE(0, 0);
    asm volatile("cp.async.commit_group;");

    const int nch = NIN / KC;
    int buf = 0;
#pragma unroll 1
    for (int ch = 0; ch < nch; ch++) {
        if (ch + 1 < nch) STAGE(buf ^ 1, (ch + 1) * KC);
        asm volatile("cp.async.commit_group;");
        asm volatile("cp.async.wait_group 1;");
        __syncthreads();                       // chunk ch ready (+ C2 on ch=0)

        const float* srow = S_sh + buf * SBUF + tid * KC;
#pragma unroll
        for (int c0 = 0; c0 < KC; c0 += 4) {
            float4 x = *reinterpret_cast<const float4*>(srow + c0);
            ull a0 = pk2(x.x, x.x), a1 = pk2(x.y, x.y);
            ull a2 = pk2(x.z, x.z), a3 = pk2(x.w, x.w);
            const int cb = (ch * KC + c0) >> 1;           // global c-pair
#pragma unroll
            for (int s2 = 0; s2 < 10; s2++) {
                ulonglong2 cA = C2[cb * 10 + s2];         // broadcast LDS.128
                ulonglong2 cB = C2[(cb + 1) * 10 + s2];
                fma2(acc[s2], a0, cA.x);
                fma2(acc[s2], a1, cA.y);
                fma2(acc[s2], a2, cB.x);
                fma2(acc[s2], a3, cB.y);
            }
        }
        buf ^= 1;
        __syncthreads();    // everyone done with old buf before restaging it
    }
#undef STAGE

    if (ok) {
#pragma unroll
        for (int s2 = 0; s2 < 10; s2++) {
            float a, b;
            upk2(acc[s2], a, b);
            outg[(size_t)(2 * s2) * T_DATA + row]     = a;
            outg[(size_t)(2 * s2 + 1) * T_DATA + row] = b;
        }
    }
}

__global__ __launch_bounds__(TGX, 2) void gemm_kernel(const float* __restrict__ Se,
                                                      const float* __restrict__ Si,
                                                      const float* __restrict__ Ce,
                                                      const float* __restrict__ Ci,
                                                      float* __restrict__ oe,
                                                      float* __restrict__ oi) {
    extern __shared__ __align__(16) char sm[];
    if (blockIdx.y == 0) gemm_body<N_E>(Se, Ce, oe, sm);
    else                 gemm_body<N_I>(Si, Ci, oi, sm);
}

// ---------------------------------------------------------------------------
// Causal conv, e/i fused through f32x2 lanes, register sliding window
// (round-7 proven core; launch_bounds bumped to 5 blocks/SM).
// Thread computes 8 CONSECUTIVE outputs; per tap: one new smem value +
// broadcast tap + 8 FFMA2 into a rotating 8-register window (static idx).
// Residue-of-8 smem layout keeps the stride-8 lane pattern conflict-free.
// ---------------------------------------------------------------------------
__global__ __launch_bounds__(256, 5) void conv_kernel(float* __restrict__ out,
                                                      const float* __restrict__ K_syn,
                                                      const float* __restrict__ tau_syn,
                                                      const float* __restrict__ delta_syn) {
    __shared__ ull sh[8 * NWC];     // 2256 packed (e,i) samples, 18048 B
    __shared__ ull ksh[KP];         // taps padded to 208 with zeros

    const int s = blockIdx.y;
    const int t0 = blockIdx.x * TTC;
    const int tid = threadIdx.x;
    const size_t sT = (size_t)s * T_DATA;

    // taps: ksh[k] = (kern_e[s,k], kern_i[s,k])
    if (tid < KP) {
        const int k = tid;
        float ae = 0.f, ai = 0.f;
        if (k < TSYN) {
            float tse = fmaxf((float)k - delta_syn[s * 2 + 0], 0.f);
            float tsi = fmaxf((float)k - delta_syn[s * 2 + 1], 0.f);
#pragma unroll
            for (int b = 0; b < NB; b++) {
                float te = tse / expf(tau_syn[b * 2 + 0]);
                float ti = tsi / expf(tau_syn[b * 2 + 1]);
                ae += K_syn[s * 6 + b * 2 + 0] * te * expf(-te);
                ai += K_syn[s * 6 + b * 2 + 1] * ti * expf(-ti);
            }
        }
        ksh[k] = pk2(ae, ai);
    }

    // fill: Lp = local sample index + 8 front-pad; t = t0 - 208 + Lp
    for (int Lp = tid; Lp < 8 * NWC; Lp += 256) {
        int t = t0 - 208 + Lp;
        float e = 0.f, ii = 0.f;
        if (t >= 0 && t < T_DATA) { e = g_e[sT + t]; ii = g_i[sT + t]; }
        sh[(Lp & 7) * NWC + (Lp >> 3)] = pk2(e, ii);
    }
    __syncthreads();

    // AT(c): sample at local offset 8*tid + c (c may be -8..215)
    //   Lp = 8*tid + c + 8  ->  sh[(c&7)*NWC + tid + 1 + (c>>3)]
#define AT(c) sh[(((c) & 7) * NWC) + tid + 1 + ((c) >> 3)]

    ull P[8], acc[8];
#pragma unroll
    for (int j = 0; j < 8; j++) {
        acc[j] = 0ULL;
        P[j] = AT(200 + j);        // window for k=0: slot m&7 holds d(m)
    }

#pragma unroll 2
    for (int kb = 0; kb < KP; kb += 8) {
#pragma unroll
        for (int r = 0; r < 8; r++) {
            ull kv = ksh[kb + r];
#pragma unroll
            for (int j = 0; j < 8; j++)
                fma2(acc[j], kv, P[(j - r) & 7]);
            // slide: load d(199 - k) into slot (199-k)&7 = 7-r
            P[7 - r] = AT(199 - kb - r);
        }
    }
#undef AT

#pragma unroll
    for (int j = 0; j < 8; j++) {
        int t = t0 + 8 * tid + j;
        if (t < T_DATA) {
            float lo, hi;
            upk2(acc[j], lo, hi);
            out[(size_t)t * SUB + s] = lo + hi;    // e-lane + i-lane
        }
    }
}

// ---------------------------------------------------------------------------
extern "C" void kernel_launch(void* const* d_in, const int* in_sizes, int n_in,
                              void* d_out, int out_size) {
    const float* S_e     = (const float*)d_in[0];
    const float* S_i     = (const float*)d_in[1];
    const float* C_syn_e = (const float*)d_in[2];
    const float* C_syn_i = (const float*)d_in[3];
    const float* K_syn   = (const float*)d_in[4];
    const float* tau_syn = (const float*)d_in[5];
    const float* delta   = (const float*)d_in[6];
    float* out = (float*)d_out;

    (void)in_sizes; (void)n_in; (void)out_size;

    float* ge; cudaGetSymbolAddress((void**)&ge, g_e);
    float* gi; cudaGetSymbolAddress((void**)&gi, g_i);

    static int smem_set = 0;
    if (!smem_set) {
        cudaFuncSetAttribute(gemm_kernel,
                             cudaFuncAttributeMaxDynamicSharedMemorySize,
                             GEMM_SMEM);
        smem_set = 1;
    }

    dim3 ggrid((T_DATA + RG - 1) / RG, 2);          // 391 x 2 (e and i)
    gemm_kernel<<<ggrid, TGX, GEMM_SMEM>>>(S_e, S_i, C_syn_e, C_syn_i, ge, gi);

    dim3 cgrid((T_DATA + TTC - 1) / TTC, SUB);      // 49 x 20
    conv_kernel<<<cgrid, 256>>>(out, K_syn, tau_syn, delta);
}

// round 11
// speedup vs baseline: 1.2265x; 1.0406x over previous
#include <cuda_runtime.h>
#include <cstdint>

#define T_DATA 100000
#define N_E    500
#define N_I    200
#define SUB    20
#define NB     3
#define TSYN   201

typedef unsigned long long ull;

// ---- GEMM config ----
#define TGX   256            // threads per block
#define RG    512            // rows per block (2 per thread)
#define KC    20             // k-chunk
#define SBUF  (RG * KC)      // floats per S stage (10240 = 40 KB)
#define CBUF  100            // ulonglong2 per C stage (10 cpairs x 10 s2 = 1.6 KB)
#define GEMM_SMEM (2 * SBUF * 4 + 2 * CBUF * 16)   // 85120 B

// ---- conv config ----
#define CTH   128            // threads per block
#define TTC   1024           // outputs per block (128 thr x 8 consecutive)
#define KP    208            // taps padded to multiple of 8
#define NWC   154            // residue-layout row width in ull: (TTC+KP)/8

// Scratch (device globals: allocation-free rule)
__device__ float g_e[(size_t)SUB * T_DATA];
__device__ float g_i[(size_t)SUB * T_DATA];
// packed C pairs: e at [0, 2500), i at [2500, 3500)
//   g_Cp[cpair*10 + s2] = { pk2(C[2s2,2cp],C[2s2+1,2cp]),
//                           pk2(C[2s2,2cp+1],C[2s2+1,2cp+1]) }
__device__ ulonglong2 g_Cp[2500 + 1000];

// ---- packed f32x2 helpers ----
__device__ __forceinline__ ull pk2(float lo, float hi) {
    ull r;
    asm("mov.b64 %0, {%1, %2};" : "=l"(r) : "f"(lo), "f"(hi));
    return r;
}
__device__ __forceinline__ void upk2(ull v, float& lo, float& hi) {
    asm("mov.b64 {%0, %1}, %2;" : "=f"(lo), "=f"(hi) : "l"(v));
}
__device__ __forceinline__ void fma2(ull& d, ull a, ull b) {
    asm("fma.rn.f32x2 %0, %1, %2, %0;" : "+l"(d) : "l"(a), "l"(b));
}
__device__ __forceinline__ uint32_t smem_u32(const void* p) {
    return (uint32_t)__cvta_generic_to_shared(p);
}
// cp.async 16B with zero-fill when !ok (src_size = 0)
__device__ __forceinline__ void cpa16(uint32_t dst, const void* src, bool ok) {
    int sz = ok ? 16 : 0;
    asm volatile("cp.async.cg.shared.global [%0], [%1], 16, %2;"
                 :: "r"(dst), "l"(src), "r"(sz));
}

// ---------------------------------------------------------------------------
// pack_C: build the pair layout consumed by the GEMM inner loop.
// ---------------------------------------------------------------------------
__global__ void pack_C(const float* __restrict__ Ce, const float* __restrict__ Ci) {
    int idx = blockIdx.x * blockDim.x + threadIdx.x;
    if (idx < 2500) {                       // e: 250 cpairs x 10 s2
        int cpair = idx / 10, s2 = idx - cpair * 10;
        int c0 = 2 * cpair;
        ulonglong2 v;
        v.x = pk2(Ce[(2 * s2) * N_E + c0],     Ce[(2 * s2 + 1) * N_E + c0]);
        v.y = pk2(Ce[(2 * s2) * N_E + c0 + 1], Ce[(2 * s2 + 1) * N_E + c0 + 1]);
        g_Cp[idx] = v;
    } else if (idx < 3500) {                // i: 100 cpairs x 10 s2
        int j = idx - 2500;
        int cpair = j / 10, s2 = j - cpair * 10;
        int c0 = 2 * cpair;
        ulonglong2 v;
        v.x = pk2(Ci[(2 * s2) * N_I + c0],     Ci[(2 * s2 + 1) * N_I + c0]);
        v.y = pk2(Ci[(2 * s2) * N_I + c0 + 1], Ci[(2 * s2 + 1) * N_I + c0 + 1]);
        g_Cp[idx] = v;
    }
}

// ---------------------------------------------------------------------------
// Tall-skinny GEMM body: in[t,s] = sum_j S[t,j] * C[s,j].
// R=2 rows/thread (512 rows/block): C-broadcast LDS per FFMA2 halved vs R=1
// -> crossbar demand below fma-pipe capacity. S staged coalesced by cp.async
// (double buffer); C chunk staged by cp.async from the prepacked global
// (1.6 KB = chunk CH's 100 entries at Cp + CH*CBUF).
// ---------------------------------------------------------------------------
template <int NIN>
__device__ __forceinline__ void gemm_body(const float* __restrict__ Sg,
                                          const ulonglong2* __restrict__ Cp,
                                          float* __restrict__ outg,
                                          char* sm) {
    float* __restrict__ S_sh = reinterpret_cast<float*>(sm);
    ulonglong2* __restrict__ C_sh = reinterpret_cast<ulonglong2*>(sm + 2 * SBUF * 4);

    const int tid = threadIdx.x;
    const int t0 = blockIdx.x * RG;
    const uint32_t s_base = smem_u32(S_sh);
    const uint32_t c_base = smem_u32(C_sh);

    // stage chunk: S 2560 float4 (10/thread, coalesced 80B runs) + C 100x16B
#define STAGE(BUF, CH)                                                        \
    {                                                                         \
        const int kc = (CH) * KC;                                             \
        _Pragma("unroll")                                                     \
        for (int q = 0; q < 10; q++) {                                        \
            int flat = q * TGX + tid;                                         \
            int rl = flat / 5, q5 = flat - rl * 5;                            \
            bool okr = (t0 + rl) < T_DATA;                                    \
            const float* src = Sg + (size_t)(okr ? (t0 + rl) : 0) * NIN       \
                               + kc + 4 * q5;                                 \
            uint32_t dst = s_base +                                           \
                (uint32_t)(((BUF) * SBUF + rl * KC + 4 * q5) * 4);            \
            cpa16(dst, src, okr);                                             \
        }                                                                     \
        if (tid < CBUF)                                                       \
            cpa16(c_base + (uint32_t)(((BUF) * CBUF + tid) * 16),             \
                  Cp + (CH) * CBUF + tid, true);                              \
    }

    ull acc0[10], acc1[10];
#pragma unroll
    for (int s2 = 0; s2 < 10; s2++) { acc0[s2] = 0ULL; acc1[s2] = 0ULL; }

    STAGE(0, 0);
    asm volatile("cp.async.commit_group;");

    const int nch = NIN / KC;
    int buf = 0;
#pragma unroll 1
    for (int ch = 0; ch < nch; ch++) {
        if (ch + 1 < nch) STAGE(buf ^ 1, ch + 1);
        asm volatile("cp.async.commit_group;");
        asm volatile("cp.async.wait_group 1;");
        __syncthreads();                        // chunk ch ready in smem

        const float* srow0 = S_sh + buf * SBUF + tid * KC;
        const float* srow1 = S_sh + buf * SBUF + (tid + TGX) * KC;
        const ulonglong2* cc = C_sh + buf * CBUF;
#pragma unroll
        for (int c0 = 0; c0 < KC; c0 += 4) {
            float4 x0 = *reinterpret_cast<const float4*>(srow0 + c0);
            float4 x1 = *reinterpret_cast<const float4*>(srow1 + c0);
            ull a00 = pk2(x0.x, x0.x), a01 = pk2(x0.y, x0.y);
            ull a02 = pk2(x0.z, x0.z), a03 = pk2(x0.w, x0.w);
            ull a10 = pk2(x1.x, x1.x), a11 = pk2(x1.y, x1.y);
            ull a12 = pk2(x1.z, x1.z), a13 = pk2(x1.w, x1.w);
            const int cpl = c0 >> 1;            // local cpair index
#pragma unroll
            for (int s2 = 0; s2 < 10; s2++) {
                ulonglong2 cA = cc[cpl * 10 + s2];         // bcast LDS.128
                ulonglong2 cB = cc[(cpl + 1) * 10 + s2];
                fma2(acc0[s2], a00, cA.x);
                fma2(acc0[s2], a01, cA.y);
                fma2(acc0[s2], a02, cB.x);
                fma2(acc0[s2], a03, cB.y);
                fma2(acc1[s2], a10, cA.x);
                fma2(acc1[s2], a11, cA.y);
                fma2(acc1[s2], a12, cB.x);
                fma2(acc1[s2], a13, cB.y);
            }
        }
        buf ^= 1;
        __syncthreads();    // all reads of old buf done before restage
    }
#undef STAGE

    const int r0 = t0 + tid;
    const int r1 = t0 + tid + TGX;
    if (r0 < T_DATA) {
#pragma unroll
        for (int s2 = 0; s2 < 10; s2++) {
            float a, b;
            upk2(acc0[s2], a, b);
            outg[(size_t)(2 * s2) * T_DATA + r0]     = a;
            outg[(size_t)(2 * s2 + 1) * T_DATA + r0] = b;
        }
    }
    if (r1 < T_DATA) {
#pragma unroll
        for (int s2 = 0; s2 < 10; s2++) {
            float a, b;
            upk2(acc1[s2], a, b);
            outg[(size_t)(2 * s2) * T_DATA + r1]     = a;
            outg[(size_t)(2 * s2 + 1) * T_DATA + r1] = b;
        }
    }
}

__global__ __launch_bounds__(TGX, 2) void gemm_kernel(const float* __restrict__ Se,
                                                      const float* __restrict__ Si,
                                                      float* __restrict__ oe,
                                                      float* __restrict__ oi) {
    extern __shared__ __align__(16) char sm[];
    if (blockIdx.y == 0) gemm_body<N_E>(Se, g_Cp,        oe, sm);
    else                 gemm_body<N_I>(Si, g_Cp + 2500, oi, sm);
}

// ---------------------------------------------------------------------------
// Causal conv, e/i fused through f32x2 lanes, register sliding window
// (proven J=8 core; 128-thr blocks on 1024-wide tiles for higher occupancy).
// Per tap: one new smem value + broadcast tap + 8 FFMA2 into a rotating
// 8-register window (static indices). Residue-of-8 smem layout keeps the
// stride-8 lane pattern conflict-free.
// ---------------------------------------------------------------------------
__global__ __launch_bounds__(CTH, 10) void conv_kernel(float* __restrict__ out,
                                                       const float* __restrict__ K_syn,
                                                       const float* __restrict__ tau_syn,
                                                       const float* __restrict__ delta_syn) {
    __shared__ ull sh[8 * NWC];     // 1232 packed (e,i) samples, 9856 B
    __shared__ ull ksh[KP];         // taps padded to 208 with zeros

    const int s = blockIdx.y;
    const int t0 = blockIdx.x * TTC;
    const int tid = threadIdx.x;
    const size_t sT = (size_t)s * T_DATA;

    // taps: ksh[k] = (kern_e[s,k], kern_i[s,k])
    for (int k = tid; k < KP; k += CTH) {
        float ae = 0.f, ai = 0.f;
        if (k < TSYN) {
            float tse = fmaxf((float)k - delta_syn[s * 2 + 0], 0.f);
            float tsi = fmaxf((float)k - delta_syn[s * 2 + 1], 0.f);
#pragma unroll
            for (int b = 0; b < NB; b++) {
                float te = tse / expf(tau_syn[b * 2 + 0]);
                float ti = tsi / expf(tau_syn[b * 2 + 1]);
                ae += K_syn[s * 6 + b * 2 + 0] * te * expf(-te);
                ai += K_syn[s * 6 + b * 2 + 1] * ti * expf(-ti);
            }
        }
        ksh[k] = pk2(ae, ai);
    }

    // fill: Lp = local sample index + 8 front-pad; t = t0 - 208 + Lp
    for (int Lp = tid; Lp < 8 * NWC; Lp += CTH) {
        int t = t0 - 208 + Lp;
        float e = 0.f, ii = 0.f;
        if (t >= 0 && t < T_DATA) { e = g_e[sT + t]; ii = g_i[sT + t]; }
        sh[(Lp & 7) * NWC + (Lp >> 3)] = pk2(e, ii);
    }
    __syncthreads();

    // AT(c): sample at local offset 8*tid + c (c may be -8..215)
    //   Lp = 8*tid + c + 8  ->  sh[(c&7)*NWC + tid + 1 + (c>>3)]
#define AT(c) sh[(((c) & 7) * NWC) + tid + 1 + ((c) >> 3)]

    ull P[8], acc[8];
#pragma unroll
    for (int j = 0; j < 8; j++) {
        acc[j] = 0ULL;
        P[j] = AT(200 + j);        // window for k=0: slot m&7 holds d(m)
    }

#pragma unroll 2
    for (int kb = 0; kb < KP; kb += 8) {
#pragma unroll
        for (int r = 0; r < 8; r++) {
            ull kv = ksh[kb + r];
#pragma unroll
            for (int j = 0; j < 8; j++)
                fma2(acc[j], kv, P[(j - r) & 7]);
            // slide: load d(199 - k) into slot (199-k)&7 = 7-r
            P[7 - r] = AT(199 - kb - r);
        }
    }
#undef AT

#pragma unroll
    for (int j = 0; j < 8; j++) {
        int t = t0 + 8 * tid + j;
        if (t < T_DATA) {
            float lo, hi;
            upk2(acc[j], lo, hi);
            out[(size_t)t * SUB + s] = lo + hi;    // e-lane + i-lane
        }
    }
}

// ---------------------------------------------------------------------------
extern "C" void kernel_launch(void* const* d_in, const int* in_sizes, int n_in,
                              void* d_out, int out_size) {
    const float* S_e     = (const float*)d_in[0];
    const float* S_i     = (const float*)d_in[1];
    const float* C_syn_e = (const float*)d_in[2];
    const float* C_syn_i = (const float*)d_in[3];
    const float* K_syn   = (const float*)d_in[4];
    const float* tau_syn = (const float*)d_in[5];
    const float* delta   = (const float*)d_in[6];
    float* out = (float*)d_out;

    (void)in_sizes; (void)n_in; (void)out_size;

    float* ge; cudaGetSymbolAddress((void**)&ge, g_e);
    float* gi; cudaGetSymbolAddress((void**)&gi, g_i);

    static int smem_set = 0;
    if (!smem_set) {
        cudaFuncSetAttribute(gemm_kernel,
                             cudaFuncAttributeMaxDynamicSharedMemorySize,
                             GEMM_SMEM);
        smem_set = 1;
    }

    pack_C<<<14, 256>>>(C_syn_e, C_syn_i);

    dim3 ggrid((T_DATA + RG - 1) / RG, 2);          // 196 x 2 (e and i)
    gemm_kernel<<<ggrid, TGX, GEMM_SMEM>>>(S_e, S_i, ge, gi);

    dim3 cgrid((T_DATA + TTC - 1) / TTC, SUB);      // 98 x 20
    conv_kernel<<<cgrid, CTH>>>(out, K_syn, tau_syn, delta);
}

// round 13
// speedup vs baseline: 1.8783x; 1.5314x over previous
#include <cuda_runtime.h>
#include <cstdint>

#define T_DATA 100000
#define N_E    500
#define N_I    200
#define SUB    20
#define NB     3
#define TSYN   201

typedef unsigned long long ull;

// ---- GEMM config ----
#define GTH    256                 // 8 warps x 16 rows = 128 rows/block
#define SSTR   36                  // smem row stride in words (== 4 mod 32)
#define S_WORDS (128 * SSTR)       // 4608 floats per S buffer
#define C_WORDS (24 * SSTR)        // 864 floats per C buffer

// ---- conv config ----
#define CTH   128
#define TTC   1024
#define KP    208
#define NWC   154

// Scratch (device globals: allocation-free rule)
__device__ float g_e[(size_t)SUB * T_DATA];
__device__ float g_i[(size_t)SUB * T_DATA];

// ---- packed f32x2 helpers (conv) ----
__device__ __forceinline__ ull pk2(float lo, float hi) {
    ull r;
    asm("mov.b64 %0, {%1, %2};" : "=l"(r) : "f"(lo), "f"(hi));
    return r;
}
__device__ __forceinline__ void upk2(ull v, float& lo, float& hi) {
    asm("mov.b64 {%0, %1}, %2;" : "=f"(lo), "=f"(hi) : "l"(v));
}
__device__ __forceinline__ void fma2(ull& d, ull a, ull b) {
    asm("fma.rn.f32x2 %0, %1, %2, %0;" : "+l"(d) : "l"(a), "l"(b));
}

// ---- GEMM helpers ----
__device__ __forceinline__ uint32_t smem_u32(const void* p) {
    return (uint32_t)__cvta_generic_to_shared(p);
}
__device__ __forceinline__ void cpa16(uint32_t dst, const void* src, bool ok) {
    int sz = ok ? 16 : 0;
    asm volatile("cp.async.cg.shared.global [%0], [%1], 16, %2;"
                 :: "r"(dst), "l"(src), "r"(sz));
}
__device__ __forceinline__ uint32_t to_tf32(float f) {
    uint32_t u;
    asm("cvt.rna.tf32.f32 %0, %1;" : "=r"(u) : "f"(f));
    return u;
}
__device__ __forceinline__ void mma_tf32(float* d, uint32_t a0, uint32_t a1,
                                         uint32_t a2, uint32_t a3,
                                         uint32_t b0, uint32_t b1) {
    asm volatile(
        "mma.sync.aligned.m16n8k8.row.col.f32.tf32.tf32.f32 "
        "{%0,%1,%2,%3}, {%4,%5,%6,%7}, {%8,%9}, {%0,%1,%2,%3};"
        : "+f"(d[0]), "+f"(d[1]), "+f"(d[2]), "+f"(d[3])
        : "r"(a0), "r"(a1), "r"(a2), "r"(a3), "r"(b0), "r"(b1));
}

// ---------------------------------------------------------------------------
// Tall-skinny GEMM via warp-level tf32 mma.sync:
//   in[t,s] = sum_j S[t,j] * C[s,j]
// M = time (16/warp), N = subunits (20 -> 24, 3 n8-tiles), K chunks of 32
// (4 ksteps), K/N zero-padded through cp.async src_size=0.
// Smem rows stride 36 words (==4 mod 32): A-frag and B-frag scalar LDS are
// perfect 32-bank permutations (bank = 4*gr + tg). cvt.rna.tf32 at fragment
// load (round-to-nearest; no truncation bias).
// ---------------------------------------------------------------------------
template <int NIN, int NCH>
__device__ __forceinline__ void gemm_body(const float* __restrict__ Sg,
                                          const float* __restrict__ Cg,
                                          float* __restrict__ outg,
                                          float* __restrict__ S_sh,
                                          float* __restrict__ C_sh) {
    const int tid = threadIdx.x;
    const int wid = tid >> 5;
    const int lid = tid & 31;
    const int gr = lid >> 2;          // groupID (0..7)
    const int tg = lid & 3;           // threadID_in_group (0..3)
    const int t0 = blockIdx.x * 128;

    const uint32_t s_base = smem_u32(S_sh);
    const uint32_t c_base = smem_u32(C_sh);

    // stage chunk CH into buffer BUF: S 128x32 (4 granules/thr), C 24x32
#define STAGE(BUF, CH)                                                        \
    {                                                                         \
        const int kc = (CH) * 32;                                             \
        _Pragma("unroll")                                                     \
        for (int q = 0; q < 4; q++) {                                         \
            int g = q * GTH + tid;                                            \
            int r = g >> 3, cg = g & 7;                                       \
            int col = kc + cg * 4;                                            \
            bool okg = ((t0 + r) < T_DATA) && (col < NIN);                    \
            cpa16(s_base + (uint32_t)(((BUF) * S_WORDS + r * SSTR + cg * 4) * 4), \
                  Sg + (size_t)(okg ? (t0 + r) : 0) * NIN + (okg ? col : 0),  \
                  okg);                                                       \
        }                                                                     \
        if (tid < 192) {                                                      \
            int r = tid >> 3, cg = tid & 7;                                   \
            int col = kc + cg * 4;                                            \
            bool okc = (r < SUB) && (col < NIN);                              \
            cpa16(c_base + (uint32_t)(((BUF) * C_WORDS + r * SSTR + cg * 4) * 4), \
                  Cg + (size_t)(okc ? r : 0) * NIN + (okc ? col : 0),         \
                  okc);                                                       \
        }                                                                     \
    }

    float d[3][4];
#pragma unroll
    for (int nt = 0; nt < 3; nt++)
#pragma unroll
        for (int r = 0; r < 4; r++) d[nt][r] = 0.f;

    STAGE(0, 0);
    asm volatile("cp.async.commit_group;");

    int buf = 0;
#pragma unroll 1
    for (int ch = 0; ch < NCH; ch++) {
        if (ch + 1 < NCH) STAGE(buf ^ 1, ch + 1);
        asm volatile("cp.async.commit_group;");
        asm volatile("cp.async.wait_group 1;");
        __syncthreads();                        // chunk ch resident

        const float* arow = S_sh + buf * S_WORDS + (wid * 16 + gr) * SSTR + tg;
        const float* brow = C_sh + buf * C_WORDS + gr * SSTR + tg;
#pragma unroll
        for (int ks = 0; ks < 4; ks++) {
            const int k0 = ks * 8;
            uint32_t a0 = to_tf32(arow[k0]);
            uint32_t a1 = to_tf32(arow[k0 + 8 * SSTR]);
            uint32_t a2 = to_tf32(arow[k0 + 4]);
            uint32_t a3 = to_tf32(arow[k0 + 4 + 8 * SSTR]);
#pragma unroll
            for (int nt = 0; nt < 3; nt++) {
                uint32_t b0 = to_tf32(brow[nt * 8 * SSTR + k0]);
                uint32_t b1 = to_tf32(brow[nt * 8 * SSTR + k0 + 4]);
                mma_tf32(d[nt], a0, a1, a2, a3, b0, b1);
            }
        }
        buf ^= 1;
        __syncthreads();                        // done reading old buf
    }
#undef STAGE

    // epilogue: D rows = time, cols = subunit; planar [s][t] scratch
    const int tlo = t0 + wid * 16 + gr;
    const int thi = tlo + 8;
#pragma unroll
    for (int nt = 0; nt < 3; nt++) {
        int c0 = nt * 8 + 2 * tg;
        int c1 = c0 + 1;
        if (c0 < SUB) {
            if (tlo < T_DATA) outg[(size_t)c0 * T_DATA + tlo] = d[nt][0];
            if (thi < T_DATA) outg[(size_t)c0 * T_DATA + thi] = d[nt][2];
        }
        if (c1 < SUB) {
            if (tlo < T_DATA) outg[(size_t)c1 * T_DATA + tlo] = d[nt][1];
            if (thi < T_DATA) outg[(size_t)c1 * T_DATA + thi] = d[nt][3];
        }
    }
}

__global__ __launch_bounds__(GTH, 4)
void gemm_kernel(const float* __restrict__ Se, const float* __restrict__ Si,
                 const float* __restrict__ Ce, const float* __restrict__ Ci,
                 float* __restrict__ oe, float* __restrict__ oi) {
    __shared__ __align__(16) float S_sh[2 * S_WORDS];   // 36864 B
    __shared__ __align__(16) float C_sh[2 * C_WORDS];   // 6912 B
    if (blockIdx.y == 0) gemm_body<N_E, 16>(Se, Ce, oe, S_sh, C_sh);
    else                 gemm_body<N_I, 7>(Si, Ci, oi, S_sh, C_sh);
}

// ---------------------------------------------------------------------------
// Causal conv (round-11 proven core, unchanged): e/i fused via f32x2 lanes,
// register sliding window, residue-of-8 smem layout.
// ---------------------------------------------------------------------------
__global__ __launch_bounds__(CTH, 10) void conv_kernel(float* __restrict__ out,
                                                       const float* __restrict__ K_syn,
                                                       const float* __restrict__ tau_syn,
                                                       const float* __restrict__ delta_syn) {
    __shared__ ull sh[8 * NWC];
    __shared__ ull ksh[KP];

    const int s = blockIdx.y;
    const int t0 = blockIdx.x * TTC;
    const int tid = threadIdx.x;
    const size_t sT = (size_t)s * T_DATA;

    for (int k = tid; k < KP; k += CTH) {
        float ae = 0.f, ai = 0.f;
        if (k < TSYN) {
            float tse = fmaxf((float)k - delta_syn[s * 2 + 0], 0.f);
            float tsi = fmaxf((float)k - delta_syn[s * 2 + 1], 0.f);
#pragma unroll
            for (int b = 0; b < NB; b++) {
                float te = tse / expf(tau_syn[b * 2 + 0]);
                float ti = tsi / expf(tau_syn[b * 2 + 1]);
                ae += K_syn[s * 6 + b * 2 + 0] * te * expf(-te);
                ai += K_syn[s * 6 + b * 2 + 1] * ti * expf(-ti);
            }
        }
        ksh[k] = pk2(ae, ai);
    }

    for (int Lp = tid; Lp < 8 * NWC; Lp += CTH) {
        int t = t0 - 208 + Lp;
        float e = 0.f, ii = 0.f;
        if (t >= 0 && t < T_DATA) { e = g_e[sT + t]; ii = g_i[sT + t]; }
        sh[(Lp & 7) * NWC + (Lp >> 3)] = pk2(e, ii);
    }
    __syncthreads();

#define AT(c) sh[(((c) & 7) * NWC) + tid + 1 + ((c) >> 3)]

    ull P[8], acc[8];
#pragma unroll
    for (int j = 0; j < 8; j++) {
        acc[j] = 0ULL;
        P[j] = AT(200 + j);
    }

#pragma unroll 2
    for (int kb = 0; kb < KP; kb += 8) {
#pragma unroll
        for (int r = 0; r < 8; r++) {
            ull kv = ksh[kb + r];
#pragma unroll
            for (int j = 0; j < 8; j++)
                fma2(acc[j], kv, P[(j - r) & 7]);
            P[7 - r] = AT(199 - kb - r);
        }
    }
#undef AT

#pragma unroll
    for (int j = 0; j < 8; j++) {
        int t = t0 + 8 * tid + j;
        if (t < T_DATA) {
            float lo, hi;
            upk2(acc[j], lo, hi);
            out[(size_t)t * SUB + s] = lo + hi;
        }
    }
}

// ---------------------------------------------------------------------------
extern "C" void kernel_launch(void* const* d_in, const int* in_sizes, int n_in,
                              void* d_out, int out_size) {
    const float* S_e     = (const float*)d_in[0];
    const float* S_i     = (const float*)d_in[1];
    const float* C_syn_e = (const float*)d_in[2];
    const float* C_syn_i = (const float*)d_in[3];
    const float* K_syn   = (const float*)d_in[4];
    const float* tau_syn = (const float*)d_in[5];
    const float* delta   = (const float*)d_in[6];
    float* out = (float*)d_out;

    (void)in_sizes; (void)n_in; (void)out_size;

    float* ge; cudaGetSymbolAddress((void**)&ge, g_e);
    float* gi; cudaGetSymbolAddress((void**)&gi, g_i);

    dim3 ggrid((T_DATA + 127) / 128, 2);            // 782 x 2 (e and i)
    gemm_kernel<<<ggrid, GTH>>>(S_e, S_i, C_syn_e, C_syn_i, ge, gi);

    dim3 cgrid((T_DATA + TTC - 1) / TTC, SUB);      // 98 x 20
    conv_kernel<<<cgrid, CTH>>>(out, K_syn, tau_syn, delta);
}